// round 4
// baseline (speedup 1.0000x reference)
#include <cuda_runtime.h>
#include <cstdint>

#define Bc    524288
#define HID   64
#define NSTEP 10

typedef unsigned long long ull;

// Scratch: c_pre = b1 + context @ W1[2:66], layout [q][B] as float4 (q = neuron/4)
__device__ float4 g_cpre[16 * Bc];

// ---------- packed f32x2 helpers ----------
__device__ __forceinline__ ull pk2(float a, float b) {
    ull r; asm("mov.b64 %0, {%1, %2};" : "=l"(r) : "f"(a), "f"(b)); return r;
}
__device__ __forceinline__ void up2(ull v, float& a, float& b) {
    asm("mov.b64 {%0, %1}, %2;" : "=f"(a), "=f"(b) : "l"(v));
}
__device__ __forceinline__ ull ffma2(ull a, ull b, ull c) {
    ull d; asm("fma.rn.f32x2 %0, %1, %2, %3;" : "=l"(d) : "l"(a), "l"(b), "l"(c)); return d;
}
__device__ __forceinline__ ull fmul2(ull a, ull b) {
    ull d; asm("mul.rn.f32x2 %0, %1, %2;" : "=l"(d) : "l"(a), "l"(b)); return d;
}
__device__ __forceinline__ ull fadd2(ull a, ull b) {
    ull d; asm("add.rn.f32x2 %0, %1, %2;" : "=l"(d) : "l"(a), "l"(b)); return d;
}
__device__ __forceinline__ ull L64(const float* p) {       // LDS.64
    return *reinterpret_cast<const ull*>(p);
}
// tanh(x) = 1 - 2/(1 + exp(2x)); ex2.approx + rcp.approx. ~1e-7 abs err, saturates safely.
__device__ __forceinline__ float ftanh(float x) {
    float e; asm("ex2.approx.f32 %0, %1;" : "=f"(e) : "f"(x * 2.885390081777927f));
    float r; asm("rcp.approx.f32 %0, %1;" : "=f"(r) : "f"(e + 1.0f));
    return fmaf(-2.0f, r, 1.0f);
}

// ---------- Kernel A: c_pre precompute (context part of layer 1, done once) ----------
__global__ __launch_bounds__(256) void cnf_pre(
    const float* __restrict__ ctx, const float* __restrict__ W1,
    const float* __restrict__ b1)
{
    __shared__ __align__(16) float sW1c[64 * 64];  // W1 rows 2..65
    __shared__ float sb1[64];
    const int tid = threadIdx.x;
    for (int i = tid; i < 4096; i += 256) sW1c[i] = W1[2 * 64 + i];
    if (tid < 64) sb1[tid] = b1[tid];
    __syncthreads();

    const int b = blockIdx.x * 256 + tid;
    float cx[64];
    const float4* c4 = reinterpret_cast<const float4*>(ctx + (size_t)b * 64);
#pragma unroll
    for (int q = 0; q < 16; q++) {
        float4 v = __ldg(&c4[q]);
        cx[4 * q] = v.x; cx[4 * q + 1] = v.y; cx[4 * q + 2] = v.z; cx[4 * q + 3] = v.w;
    }
#pragma unroll 1
    for (int q = 0; q < 16; q++) {
        float4 a = make_float4(sb1[4 * q], sb1[4 * q + 1], sb1[4 * q + 2], sb1[4 * q + 3]);
#pragma unroll
        for (int c = 0; c < 64; c++) {
            const float4 w = *reinterpret_cast<const float4*>(&sW1c[(c << 6) + 4 * q]);
            a.x = fmaf(cx[c], w.x, a.x);
            a.y = fmaf(cx[c], w.y, a.y);
            a.z = fmaf(cx[c], w.z, a.z);
            a.w = fmaf(cx[c], w.w, a.w);
        }
        g_cpre[(size_t)q * Bc + b] = a;
    }
}

// ---------- Kernel B: RK4 CNF with fused Hutchinson VJP ----------
// Dynamic smem layout (bytes):
//   [0, 16384)        sW2  : W2 row-major [m][j]
//   [16384, 49152)    sh1  : per-thread h1 spill area, [m*128 + tid] (conflict-free)
//   [49152, 51200)    aux  : W1r0|W1r1|W1t|b2 (64 floats each), W1zp|W3 (64 float2 each)
#define OFF_W2   0
#define OFF_H1   16384
#define OFF_AUX  49152
#define SMEM_BYTES 51200

__global__ __launch_bounds__(128) void cnf_main(
    const float* __restrict__ x, const float* __restrict__ eps,
    const float* __restrict__ W1, const float* __restrict__ W2,
    const float* __restrict__ b2, const float* __restrict__ W3,
    const float* __restrict__ b3, float* __restrict__ out)
{
    extern __shared__ __align__(16) unsigned char smem_raw[];
    float* sW2  = reinterpret_cast<float*>(smem_raw + OFF_W2);
    float* sh1  = reinterpret_cast<float*>(smem_raw + OFF_H1);
    float* sAux = reinterpret_cast<float*>(smem_raw + OFF_AUX);
    float* sW1r0 = sAux;           // [64]
    float* sW1r1 = sAux + 64;      // [64]
    float* sW1t  = sAux + 128;     // [64]
    float* sb2   = sAux + 192;     // [64]
    float* sW1zp = sAux + 256;     // [64][2] interleaved {W1[0][m], W1[1][m]}
    float* sW3   = sAux + 384;     // [64][2] interleaved {W3[j][0], W3[j][1]}

    const int tid = threadIdx.x;
    {
        float4* d = reinterpret_cast<float4*>(sW2);
        const float4* s = reinterpret_cast<const float4*>(W2);
        for (int i = tid; i < 1024; i += 128) d[i] = s[i];
    }
    if (tid < 64) {
        const float w0 = W1[tid], w1 = W1[64 + tid];
        sW1r0[tid] = w0; sW1r1[tid] = w1;
        sW1zp[2 * tid] = w0; sW1zp[2 * tid + 1] = w1;
        sW1t[tid]  = W1[66 * 64 + tid];
        sb2[tid]   = b2[tid];
        sW3[2 * tid] = W3[2 * tid]; sW3[2 * tid + 1] = W3[2 * tid + 1];
    }
    __syncthreads();

    const float bo0 = __ldg(&b3[0]), bo1 = __ldg(&b3[1]);
    const int b = blockIdx.x * 128 + tid;
    float* hcol = sh1 + tid;                 // this thread's private h1 column

    float z0 = x[2 * b], z1 = x[2 * b + 1], lp = 0.0f;
    const float step = -1.0f / 9.0f;

#pragma unroll 1
    for (int s = 0; s < NSTEP - 1; s++) {
        const float ti = 1.0f + s * step;
        const float hh = (1.0f + (s + 1) * step) - ti;
        float az0 = 0.f, az1 = 0.f, al = 0.f;
        float zi0 = z0, zi1 = z1;

#pragma unroll 1
        for (int k = 0; k < 4; k++) {
            const float tk = ti + ((k == 0) ? 0.0f : ((k == 3) ? hh : 0.5f * hh));
            const float2 ev = __ldg(reinterpret_cast<const float2*>(
                eps + (((size_t)(s * 4 + k)) * Bc + b) * 2));
            const float e0 = ev.x, e1 = ev.y;

            // ===== layer 1: h1 = tanh(c_pre + z0*W1r0 + z1*W1r1 + t*W1t) -> shared
            const ull z0d = pk2(zi0, zi0);
            const ull z1d = pk2(zi1, zi1);
            const ull td  = pk2(tk, tk);
#pragma unroll 4
            for (int q = 0; q < 16; q++) {
                const float4 cp = __ldg(&g_cpre[(size_t)q * Bc + b]);
                ull p0 = pk2(cp.x, cp.y), p1 = pk2(cp.z, cp.w);
                p0 = ffma2(z0d, L64(sW1r0 + 4 * q),     p0);
                p1 = ffma2(z0d, L64(sW1r0 + 4 * q + 2), p1);
                p0 = ffma2(z1d, L64(sW1r1 + 4 * q),     p0);
                p1 = ffma2(z1d, L64(sW1r1 + 4 * q + 2), p1);
                p0 = ffma2(td,  L64(sW1t  + 4 * q),     p0);
                p1 = ffma2(td,  L64(sW1t  + 4 * q + 2), p1);
                float a0, a1, a2, a3;
                up2(p0, a0, a1); up2(p1, a2, a3);
                hcol[(4 * q)     * 128] = ftanh(a0);
                hcol[(4 * q + 1) * 128] = ftanh(a1);
                hcol[(4 * q + 2) * 128] = ftanh(a2);
                hcol[(4 * q + 3) * 128] = ftanh(a3);
            }

            // ===== layer 2 forward: u2[j] (packed pairs in acc[32])
            ull acc[32];
#pragma unroll
            for (int p = 0; p < 32; p++) acc[p] = L64(sb2 + 2 * p);
#pragma unroll 4
            for (int m = 0; m < 64; m++) {
                const float hm = hcol[m * 128];
                const ull hd = pk2(hm, hm);
                const ulonglong2* wr =
                    reinterpret_cast<const ulonglong2*>(sW2 + (m << 6));
#pragma unroll
                for (int q = 0; q < 16; q++) {
                    const ulonglong2 wv = wr[q];                 // LDS.128 (broadcast)
                    acc[2 * q]     = ffma2(hd, wv.x, acc[2 * q]);
                    acc[2 * q + 1] = ffma2(hd, wv.y, acc[2 * q + 1]);
                }
            }

            // ===== output layer + du2 (overwrite acc[p] with packed du2 pair)
            const ull ep2 = pk2(e0, e1);
            ull fa0 = 0ULL, fa1 = 0ULL;
#pragma unroll
            for (int p = 0; p < 32; p++) {
                float ua, ub; up2(acc[p], ua, ub);
                const float ha = ftanh(ua), hb = ftanh(ub);
                const ull w3a = L64(sW3 + 4 * p);      // W3[2p][:]
                const ull w3b = L64(sW3 + 4 * p + 2);  // W3[2p+1][:]
                fa0 = ffma2(pk2(ha, ha), w3a, fa0);
                fa1 = ffma2(pk2(hb, hb), w3b, fa1);
                float xa, ya; up2(fmul2(ep2, w3a), xa, ya);
                float xb, yb; up2(fmul2(ep2, w3b), xb, yb);
                const float da = (xa + ya) * fmaf(-ha, ha, 1.0f);
                const float db = (xb + yb) * fmaf(-hb, hb, 1.0f);
                acc[p] = pk2(da, db);
            }
            float f0, f1; up2(fadd2(fa0, fa1), f0, f1);
            f0 += bo0; f1 += bo1;

            // ===== VJP: dh1_m = du2 . W2[m][:];  g = sum du1_m * W1[0:2][m]
            ull ga = 0ULL;
#pragma unroll 4
            for (int m = 0; m < 64; m++) {
                const ulonglong2* wr =
                    reinterpret_cast<const ulonglong2*>(sW2 + (m << 6));
                ull a0 = 0ULL, a1 = 0ULL, a2 = 0ULL, a3 = 0ULL;
#pragma unroll
                for (int t = 0; t < 8; t++) {
                    const ulonglong2 w0 = wr[2 * t];
                    const ulonglong2 w1 = wr[2 * t + 1];
                    a0 = ffma2(acc[4 * t],     w0.x, a0);
                    a1 = ffma2(acc[4 * t + 1], w0.y, a1);
                    a2 = ffma2(acc[4 * t + 2], w1.x, a2);
                    a3 = ffma2(acc[4 * t + 3], w1.y, a3);
                }
                const ull st = fadd2(fadd2(a0, a1), fadd2(a2, a3));
                float sx, sy; up2(st, sx, sy);
                const float dh1 = sx + sy;
                const float hm = hcol[m * 128];
                const float du1 = dh1 * fmaf(-hm, hm, 1.0f);
                ga = ffma2(pk2(du1, du1), L64(sW1zp + 2 * m), ga);
            }
            float g0, g1; up2(ga, g0, g1);
            const float nd = -(g0 * e0 + g1 * e1);     // -divergence

            // ===== RK4 bookkeeping
            const float wk = (k == 1 || k == 2) ? 2.0f : 1.0f;
            az0 = fmaf(wk, f0, az0);
            az1 = fmaf(wk, f1, az1);
            al  = fmaf(wk, nd, al);
            const float cin = (k == 2) ? hh : 0.5f * hh;
            zi0 = fmaf(cin, f0, z0);
            zi1 = fmaf(cin, f1, z1);
        }
        const float c6 = hh * (1.0f / 6.0f);
        z0 = fmaf(c6, az0, z0);
        z1 = fmaf(c6, az1, z1);
        lp = fmaf(c6, al, lp);
    }

    out[2 * b]      = z0;
    out[2 * b + 1]  = z1;
    out[2 * Bc + b] = lp;          // lp1 follows flattened z1
}

extern "C" void kernel_launch(void* const* d_in, const int* in_sizes, int n_in,
                              void* d_out, int out_size)
{
    (void)in_sizes; (void)n_in; (void)out_size;
    const float* x   = (const float*)d_in[0];
    const float* ctx = (const float*)d_in[1];
    const float* eps = (const float*)d_in[2];
    const float* W1  = (const float*)d_in[3];
    const float* b1  = (const float*)d_in[4];
    const float* W2  = (const float*)d_in[5];
    const float* b2  = (const float*)d_in[6];
    const float* W3  = (const float*)d_in[7];
    const float* b3  = (const float*)d_in[8];
    float* out = (float*)d_out;

    cudaFuncSetAttribute(cnf_main, cudaFuncAttributeMaxDynamicSharedMemorySize,
                         SMEM_BYTES);

    cnf_pre<<<Bc / 256, 256>>>(ctx, W1, b1);
    cnf_main<<<Bc / 128, 128, SMEM_BYTES>>>(x, eps, W1, W2, b2, W3, b3, out);
}

// round 9
// speedup vs baseline: 1.1120x; 1.1120x over previous
#include <cuda_runtime.h>
#include <cstdint>

#define Bc    524288
#define HID   64
#define NSTEP 10

typedef unsigned long long ull;

// Scratch: c_pre = b1 + context @ W1[2:66], layout [q][B] as float4 (q = neuron/4)
__device__ float4 g_cpre[16 * Bc];

// ---------- packed f32x2 helpers ----------
__device__ __forceinline__ ull pk2(float a, float b) {
    ull r; asm("mov.b64 %0, {%1, %2};" : "=l"(r) : "f"(a), "f"(b)); return r;
}
__device__ __forceinline__ void up2(ull v, float& a, float& b) {
    asm("mov.b64 {%0, %1}, %2;" : "=f"(a), "=f"(b) : "l"(v));
}
__device__ __forceinline__ ull ffma2(ull a, ull b, ull c) {
    ull d; asm("fma.rn.f32x2 %0, %1, %2, %3;" : "=l"(d) : "l"(a), "l"(b), "l"(c)); return d;
}
__device__ __forceinline__ ull fmul2(ull a, ull b) {
    ull d; asm("mul.rn.f32x2 %0, %1, %2;" : "=l"(d) : "l"(a), "l"(b)); return d;
}
__device__ __forceinline__ ull fadd2(ull a, ull b) {
    ull d; asm("add.rn.f32x2 %0, %1, %2;" : "=l"(d) : "l"(a), "l"(b)); return d;
}
__device__ __forceinline__ ull L64(const float* p) {        // LDS.64
    return *reinterpret_cast<const ull*>(p);
}
// tanh(x) = 1 - 2/(1 + exp(2x)); ex2.approx + rcp.approx. ~1e-7 abs err, saturates safely.
__device__ __forceinline__ float ftanh(float x) {
    float e; asm("ex2.approx.f32 %0, %1;" : "=f"(e) : "f"(x * 2.885390081777927f));
    float r; asm("rcp.approx.f32 %0, %1;" : "=f"(r) : "f"(e + 1.0f));
    return fmaf(-2.0f, r, 1.0f);
}

// ---------- Kernel A: c_pre precompute (context part of layer 1, done once) ----------
__global__ __launch_bounds__(256) void cnf_pre(
    const float* __restrict__ ctx, const float* __restrict__ W1,
    const float* __restrict__ b1)
{
    __shared__ __align__(16) float sW1c[64 * 64];  // W1 rows 2..65
    __shared__ float sb1[64];
    const int tid = threadIdx.x;
    for (int i = tid; i < 4096; i += 256) sW1c[i] = W1[2 * 64 + i];
    if (tid < 64) sb1[tid] = b1[tid];
    __syncthreads();

    const int b = blockIdx.x * 256 + tid;
    float cx[64];
    const float4* c4 = reinterpret_cast<const float4*>(ctx + (size_t)b * 64);
#pragma unroll
    for (int q = 0; q < 16; q++) {
        float4 v = __ldg(&c4[q]);
        cx[4 * q] = v.x; cx[4 * q + 1] = v.y; cx[4 * q + 2] = v.z; cx[4 * q + 3] = v.w;
    }
#pragma unroll 1
    for (int q = 0; q < 16; q++) {
        float4 a = make_float4(sb1[4 * q], sb1[4 * q + 1], sb1[4 * q + 2], sb1[4 * q + 3]);
#pragma unroll
        for (int c = 0; c < 64; c++) {
            const float4 w = *reinterpret_cast<const float4*>(&sW1c[(c << 6) + 4 * q]);
            a.x = fmaf(cx[c], w.x, a.x);
            a.y = fmaf(cx[c], w.y, a.y);
            a.z = fmaf(cx[c], w.z, a.z);
            a.w = fmaf(cx[c], w.w, a.w);
        }
        g_cpre[(size_t)q * Bc + b] = a;
    }
}

// ---------- Kernel B: RK4 CNF with fused forward-mode (JVP) Hutchinson estimate ----------
// div = e^T (J e), propagated as a tangent alongside the forward pass:
//   s1[m]  = e0*W1[0,m] + e1*W1[1,m]            (layer-1 tangent, z-only)
//   th1[m] = (1 - h1[m]^2) * s1[m]
//   u2[j]  = sum_m h1[m]  * W2[m,j]  ; t2[j] = sum_m th1[m] * W2[m,j]   <- ONE W2 pass
//   f      = sum_j tanh(u2)[j]*W3[j,:] + b3
//   Je     = sum_j (1-tanh(u2)^2)[j]*t2[j]*W3[j,:] ;  div = e . Je
__global__ __launch_bounds__(128) void cnf_main(
    const float* __restrict__ x, const float* __restrict__ eps,
    const float* __restrict__ W1, const float* __restrict__ W2,
    const float* __restrict__ b2, const float* __restrict__ W3,
    const float* __restrict__ b3, float* __restrict__ out)
{
    __shared__ __align__(16) float sW2[64 * 64];   // [m][j]
    __shared__ __align__(16) float sW1r0[64];      // W1[0][j]
    __shared__ __align__(16) float sW1r1[64];      // W1[1][j]
    __shared__ __align__(16) float sW1t[64];       // W1[66][j]
    __shared__ __align__(16) float sb2[64];
    __shared__ __align__(16) float sW3[128];       // interleaved {W3[j][0], W3[j][1]}

    const int tid = threadIdx.x;
    {
        float4* d = reinterpret_cast<float4*>(sW2);
        const float4* s = reinterpret_cast<const float4*>(W2);
        for (int i = tid; i < 1024; i += 128) d[i] = s[i];
    }
    if (tid < 64) {
        sW1r0[tid] = W1[tid];
        sW1r1[tid] = W1[64 + tid];
        sW1t[tid]  = W1[66 * 64 + tid];
        sb2[tid]   = b2[tid];
        sW3[2 * tid]     = W3[2 * tid];
        sW3[2 * tid + 1] = W3[2 * tid + 1];
    }
    __syncthreads();

    const float bo0 = __ldg(&b3[0]), bo1 = __ldg(&b3[1]);
    const int b = blockIdx.x * 128 + tid;

    float z0 = x[2 * b], z1 = x[2 * b + 1], lp = 0.0f;
    const float step = -1.0f / 9.0f;

#pragma unroll 1
    for (int s = 0; s < NSTEP - 1; s++) {
        const float ti = 1.0f + s * step;
        const float hh = (1.0f + (s + 1) * step) - ti;
        float az0 = 0.f, az1 = 0.f, al = 0.f;
        float zi0 = z0, zi1 = z1;

#pragma unroll 1
        for (int k = 0; k < 4; k++) {
            const float tk = ti + ((k == 0) ? 0.0f : ((k == 3) ? hh : 0.5f * hh));
            const float2 ev = __ldg(reinterpret_cast<const float2*>(
                eps + (((size_t)(s * 4 + k)) * Bc + b) * 2));
            const float e0 = ev.x, e1 = ev.y;

            const ull z0d = pk2(zi0, zi0);
            const ull z1d = pk2(zi1, zi1);
            const ull tdp = pk2(tk, tk);
            const ull e0d = pk2(e0, e0);
            const ull e1d = pk2(e1, e1);

            // packed j-pair accumulators: value path (u2) and tangent path (t2)
            ull accu[32], acct[32];
#pragma unroll
            for (int p = 0; p < 32; p++) { accu[p] = L64(sb2 + 2 * p); acct[p] = 0ULL; }

            // ===== fused layer 1 + layer 2 rank-1 updates (single pass over W2)
#pragma unroll 1
            for (int q = 0; q < 16; q++) {
                const float4 cp = __ldg(&g_cpre[(size_t)q * Bc + b]);
                const ull r0a = L64(sW1r0 + 4 * q), r0b = L64(sW1r0 + 4 * q + 2);
                const ull r1a = L64(sW1r1 + 4 * q), r1b = L64(sW1r1 + 4 * q + 2);
                const ull tta = L64(sW1t  + 4 * q), ttb = L64(sW1t  + 4 * q + 2);
                ull p0 = pk2(cp.x, cp.y), p1 = pk2(cp.z, cp.w);
                p0 = ffma2(z0d, r0a, p0);  p1 = ffma2(z0d, r0b, p1);
                p0 = ffma2(z1d, r1a, p0);  p1 = ffma2(z1d, r1b, p1);
                p0 = ffma2(tdp, tta, p0);  p1 = ffma2(tdp, ttb, p1);
                // layer-1 tangent: s1 = e0*W1r0 + e1*W1r1 (same operands, no extra LDS)
                ull sa = fmul2(e0d, r0a);  sa = ffma2(e1d, r1a, sa);
                ull sb = fmul2(e0d, r0b);  sb = ffma2(e1d, r1b, sb);

                float u4[4], s4[4];
                up2(p0, u4[0], u4[1]); up2(p1, u4[2], u4[3]);
                up2(sa, s4[0], s4[1]); up2(sb, s4[2], s4[3]);

#pragma unroll
                for (int r = 0; r < 4; r++) {
                    const int m = 4 * q + r;
                    const float h  = ftanh(u4[r]);
                    const float th = s4[r] * fmaf(-h, h, 1.0f);
                    const ull hd  = pk2(h, h);
                    const ull thd = pk2(th, th);
                    const ulonglong2* wr =
                        reinterpret_cast<const ulonglong2*>(sW2 + (m << 6));
#pragma unroll
                    for (int p = 0; p < 16; p++) {
                        const ulonglong2 wv = wr[p];        // LDS.128 broadcast
                        accu[2 * p]     = ffma2(hd,  wv.x, accu[2 * p]);
                        accu[2 * p + 1] = ffma2(hd,  wv.y, accu[2 * p + 1]);
                        acct[2 * p]     = ffma2(thd, wv.x, acct[2 * p]);
                        acct[2 * p + 1] = ffma2(thd, wv.y, acct[2 * p + 1]);
                    }
                }
            }

            // ===== output layer: f = h2@W3 + b3 ; Je = ((1-h2^2)*t2)@W3
            ull fa0 = 0ULL, fa1 = 0ULL, ja0 = 0ULL, ja1 = 0ULL;
#pragma unroll
            for (int p = 0; p < 32; p++) {
                float ua, ub; up2(accu[p], ua, ub);
                float ta, tb; up2(acct[p], ta, tb);
                const float ha = ftanh(ua), hb = ftanh(ub);
                const float ca = ta * fmaf(-ha, ha, 1.0f);
                const float cb = tb * fmaf(-hb, hb, 1.0f);
                const ull w3a = L64(sW3 + 4 * p);       // W3[2p][:]
                const ull w3b = L64(sW3 + 4 * p + 2);   // W3[2p+1][:]
                fa0 = ffma2(pk2(ha, ha), w3a, fa0);
                fa1 = ffma2(pk2(hb, hb), w3b, fa1);
                ja0 = ffma2(pk2(ca, ca), w3a, ja0);
                ja1 = ffma2(pk2(cb, cb), w3b, ja1);
            }
            float f0, f1; up2(fadd2(fa0, fa1), f0, f1);
            f0 += bo0; f1 += bo1;
            float je0, je1; up2(fadd2(ja0, ja1), je0, je1);
            const float nd = -(je0 * e0 + je1 * e1);    // -divergence

            // ===== RK4 bookkeeping
            const float wk = (k == 1 || k == 2) ? 2.0f : 1.0f;
            az0 = fmaf(wk, f0, az0);
            az1 = fmaf(wk, f1, az1);
            al  = fmaf(wk, nd, al);
            const float cin = (k == 2) ? hh : 0.5f * hh;
            zi0 = fmaf(cin, f0, z0);
            zi1 = fmaf(cin, f1, z1);
        }
        const float c6 = hh * (1.0f / 6.0f);
        z0 = fmaf(c6, az0, z0);
        z1 = fmaf(c6, az1, z1);
        lp = fmaf(c6, al, lp);
    }

    out[2 * b]      = z0;
    out[2 * b + 1]  = z1;
    out[2 * Bc + b] = lp;          // lp1 follows flattened z1
}

extern "C" void kernel_launch(void* const* d_in, const int* in_sizes, int n_in,
                              void* d_out, int out_size)
{
    (void)in_sizes; (void)n_in; (void)out_size;
    const float* x   = (const float*)d_in[0];
    const float* ctx = (const float*)d_in[1];
    const float* eps = (const float*)d_in[2];
    const float* W1  = (const float*)d_in[3];
    const float* b1  = (const float*)d_in[4];
    const float* W2  = (const float*)d_in[5];
    const float* b2  = (const float*)d_in[6];
    const float* W3  = (const float*)d_in[7];
    const float* b3  = (const float*)d_in[8];
    float* out = (float*)d_out;

    cnf_pre<<<Bc / 256, 256>>>(ctx, W1, b1);
    cnf_main<<<Bc / 128, 128>>>(x, eps, W1, W2, b2, W3, b3, out);
}

// round 12
// speedup vs baseline: 1.2297x; 1.1059x over previous
#include <cuda_runtime.h>
#include <cstdint>

#define Bc    524288
#define HID   64
#define NSTEP 10

typedef unsigned long long ull;

// Scratch: c_pre = b1 + context @ W1[2:66], layout [q][B] as float4 (q = neuron/4)
__device__ float4 g_cpre[16 * Bc];

// ---------- packed f32x2 helpers ----------
__device__ __forceinline__ ull pk2(float a, float b) {
    ull r; asm("mov.b64 %0, {%1, %2};" : "=l"(r) : "f"(a), "f"(b)); return r;
}
__device__ __forceinline__ void up2(ull v, float& a, float& b) {
    asm("mov.b64 {%0, %1}, %2;" : "=f"(a), "=f"(b) : "l"(v));
}
__device__ __forceinline__ ull ffma2(ull a, ull b, ull c) {
    ull d; asm("fma.rn.f32x2 %0, %1, %2, %3;" : "=l"(d) : "l"(a), "l"(b), "l"(c)); return d;
}
__device__ __forceinline__ ull fmul2(ull a, ull b) {
    ull d; asm("mul.rn.f32x2 %0, %1, %2;" : "=l"(d) : "l"(a), "l"(b)); return d;
}
__device__ __forceinline__ ull fadd2(ull a, ull b) {
    ull d; asm("add.rn.f32x2 %0, %1, %2;" : "=l"(d) : "l"(a), "l"(b)); return d;
}
__device__ __forceinline__ ull L64(const float* p) {        // LDS.64
    return *reinterpret_cast<const ull*>(p);
}
// tanh(x) = 1 - 2/(1 + exp(2x)); ex2.approx + rcp.approx. ~1e-7 abs err, saturates safely.
__device__ __forceinline__ float ftanh(float x) {
    float e; asm("ex2.approx.f32 %0, %1;" : "=f"(e) : "f"(x * 2.885390081777927f));
    float r; asm("rcp.approx.f32 %0, %1;" : "=f"(r) : "f"(e + 1.0f));
    return fmaf(-2.0f, r, 1.0f);
}

// ---------- Kernel A: c_pre precompute (context part of layer 1, done once) ----------
__global__ __launch_bounds__(256) void cnf_pre(
    const float* __restrict__ ctx, const float* __restrict__ W1,
    const float* __restrict__ b1)
{
    __shared__ __align__(16) float sW1c[64 * 64];  // W1 rows 2..65
    __shared__ float sb1[64];
    const int tid = threadIdx.x;
    for (int i = tid; i < 4096; i += 256) sW1c[i] = W1[2 * 64 + i];
    if (tid < 64) sb1[tid] = b1[tid];
    __syncthreads();

    const int b = blockIdx.x * 256 + tid;
    float cx[64];
    const float4* c4 = reinterpret_cast<const float4*>(ctx + (size_t)b * 64);
#pragma unroll
    for (int q = 0; q < 16; q++) {
        float4 v = __ldg(&c4[q]);
        cx[4 * q] = v.x; cx[4 * q + 1] = v.y; cx[4 * q + 2] = v.z; cx[4 * q + 3] = v.w;
    }
#pragma unroll 1
    for (int q = 0; q < 16; q++) {
        float4 a = make_float4(sb1[4 * q], sb1[4 * q + 1], sb1[4 * q + 2], sb1[4 * q + 3]);
#pragma unroll
        for (int c = 0; c < 64; c++) {
            const float4 w = *reinterpret_cast<const float4*>(&sW1c[(c << 6) + 4 * q]);
            a.x = fmaf(cx[c], w.x, a.x);
            a.y = fmaf(cx[c], w.y, a.y);
            a.z = fmaf(cx[c], w.z, a.z);
            a.w = fmaf(cx[c], w.w, a.w);
        }
        g_cpre[(size_t)q * Bc + b] = a;
    }
}

// ---------- Kernel B: RK4 CNF, forward-mode (JVP) Hutchinson, j-split for occupancy ----
// div = e^T (J e) via tangent propagation (one W2 pass per j-half):
//   s1[m]  = e0*W1[0,m] + e1*W1[1,m]
//   th1[m] = (1 - h1[m]^2) * s1[m]
//   u2[j]  = sum_m h1[m]*W2[m,j] ; t2[j] = sum_m th1[m]*W2[m,j]
//   f = tanh(u2)@W3 + b3 ;  Je = ((1-tanh(u2)^2)*t2)@W3 ;  div = e.Je
// The j range is processed in two halves of 32 so the packed accumulator file is
// 16+16 ull (64 regs), letting 3 CTAs co-reside per SM. Layer 1 is recomputed per
// half (cheap; c_pre LDGs are L1 hits).
__global__ __launch_bounds__(128, 3) void cnf_main(
    const float* __restrict__ x, const float* __restrict__ eps,
    const float* __restrict__ W1, const float* __restrict__ W2,
    const float* __restrict__ b2, const float* __restrict__ W3,
    const float* __restrict__ b3, float* __restrict__ out)
{
    __shared__ __align__(16) float sW2[64 * 64];   // [m][j]
    __shared__ __align__(16) float sW1r0[64];      // W1[0][j]
    __shared__ __align__(16) float sW1r1[64];      // W1[1][j]
    __shared__ __align__(16) float sW1t[64];       // W1[66][j]
    __shared__ __align__(16) float sb2[64];
    __shared__ __align__(16) float sW3[128];       // interleaved {W3[j][0], W3[j][1]}

    const int tid = threadIdx.x;
    {
        float4* d = reinterpret_cast<float4*>(sW2);
        const float4* s = reinterpret_cast<const float4*>(W2);
        for (int i = tid; i < 1024; i += 128) d[i] = s[i];
    }
    if (tid < 64) {
        sW1r0[tid] = W1[tid];
        sW1r1[tid] = W1[64 + tid];
        sW1t[tid]  = W1[66 * 64 + tid];
        sb2[tid]   = b2[tid];
        sW3[2 * tid]     = W3[2 * tid];
        sW3[2 * tid + 1] = W3[2 * tid + 1];
    }
    __syncthreads();

    const float bo0 = __ldg(&b3[0]), bo1 = __ldg(&b3[1]);
    const int b = blockIdx.x * 128 + tid;

    float z0 = x[2 * b], z1 = x[2 * b + 1], lp = 0.0f;
    const float step = -1.0f / 9.0f;

#pragma unroll 1
    for (int s = 0; s < NSTEP - 1; s++) {
        const float ti = 1.0f + s * step;
        const float hh = (1.0f + (s + 1) * step) - ti;
        float az0 = 0.f, az1 = 0.f, al = 0.f;
        float zi0 = z0, zi1 = z1;

#pragma unroll 1
        for (int k = 0; k < 4; k++) {
            const float tk = ti + ((k == 0) ? 0.0f : ((k == 3) ? hh : 0.5f * hh));
            const float2 ev = __ldg(reinterpret_cast<const float2*>(
                eps + (((size_t)(s * 4 + k)) * Bc + b) * 2));
            const float e0 = ev.x, e1 = ev.y;

            const ull z0d = pk2(zi0, zi0);
            const ull z1d = pk2(zi1, zi1);
            const ull tdp = pk2(tk, tk);
            const ull e0d = pk2(e0, e0);
            const ull e1d = pk2(e1, e1);

            ull fa0 = 0ULL, fa1 = 0ULL, ja0 = 0ULL, ja1 = 0ULL;

#pragma unroll 1
            for (int jh = 0; jh < 2; jh++) {
                const int jo = jh << 5;              // j offset (floats) of this half
                const float* w2h = sW2 + jo;

                // packed j-pair accumulators for this half: value + tangent
                ull accu[16], acct[16];
#pragma unroll
                for (int p = 0; p < 16; p++) {
                    accu[p] = L64(sb2 + jo + 2 * p);
                    acct[p] = 0ULL;
                }

                // fused layer 1 (recomputed per half) + rank-1 updates over half rows
#pragma unroll 1
                for (int q = 0; q < 16; q++) {
                    const float4 cp = __ldg(&g_cpre[(size_t)q * Bc + b]);
                    const ull r0a = L64(sW1r0 + 4 * q), r0b = L64(sW1r0 + 4 * q + 2);
                    const ull r1a = L64(sW1r1 + 4 * q), r1b = L64(sW1r1 + 4 * q + 2);
                    const ull tta = L64(sW1t  + 4 * q), ttb = L64(sW1t  + 4 * q + 2);
                    ull p0 = pk2(cp.x, cp.y), p1 = pk2(cp.z, cp.w);
                    p0 = ffma2(z0d, r0a, p0);  p1 = ffma2(z0d, r0b, p1);
                    p0 = ffma2(z1d, r1a, p0);  p1 = ffma2(z1d, r1b, p1);
                    p0 = ffma2(tdp, tta, p0);  p1 = ffma2(tdp, ttb, p1);
                    // layer-1 tangent: s1 = e0*W1r0 + e1*W1r1 (same operands)
                    ull sa = fmul2(e0d, r0a);  sa = ffma2(e1d, r1a, sa);
                    ull sb = fmul2(e0d, r0b);  sb = ffma2(e1d, r1b, sb);

                    float u4[4], s4[4];
                    up2(p0, u4[0], u4[1]); up2(p1, u4[2], u4[3]);
                    up2(sa, s4[0], s4[1]); up2(sb, s4[2], s4[3]);

#pragma unroll
                    for (int r = 0; r < 4; r++) {
                        const int m = 4 * q + r;
                        const float h  = ftanh(u4[r]);
                        const float th = s4[r] * fmaf(-h, h, 1.0f);
                        const ull hd  = pk2(h, h);
                        const ull thd = pk2(th, th);
                        const ulonglong2* wr =
                            reinterpret_cast<const ulonglong2*>(w2h + (m << 6));
#pragma unroll
                        for (int p = 0; p < 8; p++) {
                            const ulonglong2 wv = wr[p];    // LDS.128 broadcast
                            accu[2 * p]     = ffma2(hd,  wv.x, accu[2 * p]);
                            accu[2 * p + 1] = ffma2(hd,  wv.y, accu[2 * p + 1]);
                            acct[2 * p]     = ffma2(thd, wv.x, acct[2 * p]);
                            acct[2 * p + 1] = ffma2(thd, wv.y, acct[2 * p + 1]);
                        }
                    }
                }

                // output-layer epilogue for this half
                const float* w3h = sW3 + 2 * jo;
#pragma unroll
                for (int p = 0; p < 16; p++) {
                    float ua, ub; up2(accu[p], ua, ub);
                    float ta, tb; up2(acct[p], ta, tb);
                    const float ha = ftanh(ua), hb = ftanh(ub);
                    const float ca = ta * fmaf(-ha, ha, 1.0f);
                    const float cb = tb * fmaf(-hb, hb, 1.0f);
                    const ull w3a = L64(w3h + 4 * p);
                    const ull w3b = L64(w3h + 4 * p + 2);
                    fa0 = ffma2(pk2(ha, ha), w3a, fa0);
                    fa1 = ffma2(pk2(hb, hb), w3b, fa1);
                    ja0 = ffma2(pk2(ca, ca), w3a, ja0);
                    ja1 = ffma2(pk2(cb, cb), w3b, ja1);
                }
            }

            float f0, f1; up2(fadd2(fa0, fa1), f0, f1);
            f0 += bo0; f1 += bo1;
            float je0, je1; up2(fadd2(ja0, ja1), je0, je1);
            const float nd = -(je0 * e0 + je1 * e1);    // -divergence

            // ===== RK4 bookkeeping
            const float wk = (k == 1 || k == 2) ? 2.0f : 1.0f;
            az0 = fmaf(wk, f0, az0);
            az1 = fmaf(wk, f1, az1);
            al  = fmaf(wk, nd, al);
            const float cin = (k == 2) ? hh : 0.5f * hh;
            zi0 = fmaf(cin, f0, z0);
            zi1 = fmaf(cin, f1, z1);
        }
        const float c6 = hh * (1.0f / 6.0f);
        z0 = fmaf(c6, az0, z0);
        z1 = fmaf(c6, az1, z1);
        lp = fmaf(c6, al, lp);
    }

    out[2 * b]      = z0;
    out[2 * b + 1]  = z1;
    out[2 * Bc + b] = lp;          // lp1 follows flattened z1
}

extern "C" void kernel_launch(void* const* d_in, const int* in_sizes, int n_in,
                              void* d_out, int out_size)
{
    (void)in_sizes; (void)n_in; (void)out_size;
    const float* x   = (const float*)d_in[0];
    const float* ctx = (const float*)d_in[1];
    const float* eps = (const float*)d_in[2];
    const float* W1  = (const float*)d_in[3];
    const float* b1  = (const float*)d_in[4];
    const float* W2  = (const float*)d_in[5];
    const float* b2  = (const float*)d_in[6];
    const float* W3  = (const float*)d_in[7];
    const float* b3  = (const float*)d_in[8];
    float* out = (float*)d_out;

    cnf_pre<<<Bc / 256, 256>>>(ctx, W1, b1);
    cnf_main<<<Bc / 128, 128>>>(x, eps, W1, W2, b2, W3, b3, out);
}